// round 3
// baseline (speedup 1.0000x reference)
#include <cuda_runtime.h>

// DeepFilterNet DF coef op, GB300 — R3: float4 + ILP=4 flat kernel.
// spec  : [B=32, 1, T=1000, F=481, 2] f32
// coefs : [B, T, 5, 96, 2] f32
// alpha : [B, T, 1] f32
// out   : same as spec; first 96 bins = 5-tap complex FIR blended with alpha.
//
// Each thread handles 4 float4 pairs (stride blockDim between them), issuing
// all 4 loads before consuming -> MLP_p1=4 on the dominant passthrough path.
// DF-region lines keep default caching (L2 absorbs 5x tap reuse); pure
// stream-once traffic uses __ldcs/__stcs.

#define B_DIM 32
#define T_DIM 1000
#define F_DIM 481
#define F_DF 96
#define ORDER 5

#define NPAIRS ((B_DIM * T_DIM * F_DIM) / 2)   // 7,696,000
#define TPB 256
#define ILP 4

__device__ __forceinline__ float2 df_elem(
    const float2* __restrict__ spec,
    const float2* __restrict__ coefs,
    const float*  __restrict__ alpha,
    int bt, int f, float2 s)
{
    int t = bt % T_DIM;
    const float2* cptr = coefs + (size_t)bt * (ORDER * F_DF) + f;

    float re = 0.0f, im = 0.0f;
    #pragma unroll
    for (int i = 0; i < ORDER; i++) {
        int tt = t + i - 2;                       // ORDER - LOOKAHEAD - 1 = 2
        float2 w = make_float2(0.0f, 0.0f);
        if (tt >= 0 && tt < T_DIM)
            w = spec[(size_t)(bt + i - 2) * F_DIM + f];
        float2 c = cptr[(size_t)i * F_DF];
        re = fmaf(w.x, c.x, re);
        re = fmaf(-w.y, c.y, re);
        im = fmaf(w.y, c.x, im);
        im = fmaf(w.x, c.y, im);
    }

    float a  = alpha[bt];
    float na = 1.0f - a;
    return make_float2(fmaf(re, a, s.x * na), fmaf(im, a, s.y * na));
}

__global__ void __launch_bounds__(TPB) df_coef_kernel(
    const float4* __restrict__ spec4,
    const float2* __restrict__ spec2,
    const float2* __restrict__ coefs,
    const float*  __restrict__ alpha,
    float4* __restrict__ out4)
{
    const int p_base = blockIdx.x * (TPB * ILP) + threadIdx.x;

    float4 s[ILP];
    int    bt[ILP], f0[ILP];
    bool   fast[ILP], valid[ILP];

    // Phase 1: index math + front-batched loads (4 LDG.128 in flight).
    #pragma unroll
    for (int j = 0; j < ILP; j++) {
        int p = p_base + j * TPB;
        valid[j] = (p < NPAIRS);
        int e0 = 2 * p;
        int b  = e0 / F_DIM;
        bt[j] = b;
        f0[j] = e0 - b * F_DIM;
        fast[j] = (f0[j] >= F_DF) && (f0[j] < F_DIM - 1);
        if (valid[j])
            s[j] = fast[j] ? __ldcs(&spec4[p]) : spec4[p];
    }

    // Phase 2: consume.
    #pragma unroll
    for (int j = 0; j < ILP; j++) {
        if (!valid[j]) continue;
        int p = p_base + j * TPB;

        if (fast[j]) {                       // pure passthrough pair
            __stcs(&out4[p], s[j]);
            continue;
        }

        float2 s0 = make_float2(s[j].x, s[j].y);
        float2 s1 = make_float2(s[j].z, s[j].w);

        float2 r0 = (f0[j] < F_DF)
                  ? df_elem(spec2, coefs, alpha, bt[j], f0[j], s0) : s0;

        int bt1 = bt[j], f1 = f0[j] + 1;
        if (f0[j] == F_DIM - 1) { bt1 = bt[j] + 1; f1 = 0; }
        float2 r1 = (f1 < F_DF)
                  ? df_elem(spec2, coefs, alpha, bt1, f1, s1) : s1;

        __stcs(&out4[p], make_float4(r0.x, r0.y, r1.x, r1.y));
    }
}

extern "C" void kernel_launch(void* const* d_in, const int* in_sizes, int n_in,
                              void* d_out, int out_size)
{
    const float4* spec4 = (const float4*)d_in[0];
    const float2* spec2 = (const float2*)d_in[0];
    const float2* coefs = (const float2*)d_in[1];
    const float*  alpha = (const float*)d_in[2];

    const int blocks = (NPAIRS + TPB * ILP - 1) / (TPB * ILP);   // 7516
    df_coef_kernel<<<blocks, TPB>>>(spec4, spec2, coefs, alpha, (float4*)d_out);
}

// round 4
// speedup vs baseline: 1.1215x; 1.1215x over previous
#include <cuda_runtime.h>

// DeepFilterNet DF coef op, GB300 — R4: R2 shape + ILP=2 + streaming coefs.
// spec  : [B=32, 1, T=1000, F=481, 2] f32
// coefs : [B, T, 5, 96, 2] f32   (stream-once -> __ldcs, don't thrash L2)
// alpha : [B, T, 1] f32          (96x reuse -> default cache)
// out   : same as spec; first 96 bins = 5-tap complex FIR blended with alpha.
//
// Flat float4 pairing (always 16B-aligned). Each thread does 2 pairs
// (p, p+TPB) within a 2*TPB-pair block chunk, front-batching both loads.
// Spec DF-region loads stay default-cached so L2 holds the 5x tap reuse.

#define B_DIM 32
#define T_DIM 1000
#define F_DIM 481
#define F_DF 96
#define ORDER 5

#define NPAIRS ((B_DIM * T_DIM * F_DIM) / 2)   // 7,696,000
#define TPB 256
#define ILP 2

__device__ __forceinline__ float2 df_elem(
    const float2* __restrict__ spec,
    const float2* __restrict__ coefs,
    const float*  __restrict__ alpha,
    int bt, int f, float2 s)
{
    int t = bt % T_DIM;
    const float2* cptr = coefs + (size_t)bt * (ORDER * F_DF) + f;

    float re = 0.0f, im = 0.0f;
    #pragma unroll
    for (int i = 0; i < ORDER; i++) {
        int tt = t + i - 2;                       // ORDER - LOOKAHEAD - 1 = 2
        float2 w = make_float2(0.0f, 0.0f);
        if (tt >= 0 && tt < T_DIM)
            w = spec[(size_t)(bt + i - 2) * F_DIM + f];
        float2 c = __ldcs(&cptr[(size_t)i * F_DF]);   // stream-once
        re = fmaf(w.x, c.x, re);
        re = fmaf(-w.y, c.y, re);
        im = fmaf(w.y, c.x, im);
        im = fmaf(w.x, c.y, im);
    }

    float a  = alpha[bt];
    float na = 1.0f - a;
    return make_float2(fmaf(re, a, s.x * na), fmaf(im, a, s.y * na));
}

__global__ void __launch_bounds__(TPB) df_coef_kernel(
    const float4* __restrict__ spec4,
    const float2* __restrict__ spec2,
    const float2* __restrict__ coefs,
    const float*  __restrict__ alpha,
    float4* __restrict__ out4)
{
    const int p_base = blockIdx.x * (TPB * ILP) + threadIdx.x;

    float4 s[ILP];
    int    bt[ILP], f0[ILP];
    bool   fast[ILP], valid[ILP];

    // Front-batch both loads (2 LDG.128 in flight per thread).
    #pragma unroll
    for (int j = 0; j < ILP; j++) {
        int p = p_base + j * TPB;
        valid[j] = (p < NPAIRS);
        int e0 = 2 * p;
        int b  = e0 / F_DIM;
        bt[j] = b;
        f0[j] = e0 - b * F_DIM;
        fast[j] = (f0[j] >= F_DF) && (f0[j] < F_DIM - 1);
        if (valid[j])
            s[j] = fast[j] ? __ldcs(&spec4[p]) : spec4[p];
    }

    #pragma unroll
    for (int j = 0; j < ILP; j++) {
        if (!valid[j]) continue;
        int p = p_base + j * TPB;

        if (fast[j]) {                        // pure passthrough pair
            __stcs(&out4[p], s[j]);
            continue;
        }

        float2 s0 = make_float2(s[j].x, s[j].y);
        float2 s1 = make_float2(s[j].z, s[j].w);

        float2 r0 = (f0[j] < F_DF)
                  ? df_elem(spec2, coefs, alpha, bt[j], f0[j], s0) : s0;

        int bt1 = bt[j], f1 = f0[j] + 1;
        if (f0[j] == F_DIM - 1) { bt1 = bt[j] + 1; f1 = 0; }
        float2 r1 = (f1 < F_DF)
                  ? df_elem(spec2, coefs, alpha, bt1, f1, s1) : s1;

        __stcs(&out4[p], make_float4(r0.x, r0.y, r1.x, r1.y));
    }
}

extern "C" void kernel_launch(void* const* d_in, const int* in_sizes, int n_in,
                              void* d_out, int out_size)
{
    const float4* spec4 = (const float4*)d_in[0];
    const float2* spec2 = (const float2*)d_in[0];
    const float2* coefs = (const float2*)d_in[1];
    const float*  alpha = (const float*)d_in[2];

    const int blocks = (NPAIRS + TPB * ILP - 1) / (TPB * ILP);   // 15032
    df_coef_kernel<<<blocks, TPB>>>(spec4, spec2, coefs, alpha, (float4*)d_out);
}

// round 5
// speedup vs baseline: 1.2269x; 1.0940x over previous
#include <cuda_runtime.h>

// DeepFilterNet DF coef op, GB300 — R5: block-role split (DF blocks + copy blocks).
// spec  : [B=32, 1, T=1000, F=481, 2] f32
// coefs : [B, T, 5, 96, 2] f32
// alpha : [B, T, 1] f32
// out   : same as spec; first 96 bins = 5-tap complex FIR blended with alpha.
//
// Pair-space (float4 = 2 complex elems) partitioned exactly by role.
// Per rowpair (rows 2rp, 2rp+1): 97 "slow" pairs touch DF bins, 384 are pure
// upper-bin passthrough. Slow blocks first (long chains overlap the copy).
// No ILP, coefs default-cached (both proven by R3/R4 regressions).

#define B_DIM 32
#define T_DIM 1000
#define F_DIM 481
#define F_DF 96
#define ORDER 5

#define NROWPAIR 16000                 // 32000 rows / 2
#define NSLOW    (NROWPAIR * 97)       // 1,552,000 pairs
#define NFAST    (NROWPAIR * 384)      // 6,144,000 pairs
#define TPB      256
#define SLOW_BLOCKS ((NSLOW + TPB - 1) / TPB)   // 6063
#define FAST_BLOCKS (NFAST / TPB)               // 24000

__device__ __forceinline__ float2 df_elem(
    const float2* __restrict__ spec,
    const float2* __restrict__ coefs,
    const float*  __restrict__ alpha,
    int bt, int f, float2 s)
{
    int t = bt % T_DIM;
    const float2* cptr = coefs + (size_t)bt * (ORDER * F_DF) + f;

    float re = 0.0f, im = 0.0f;
    #pragma unroll
    for (int i = 0; i < ORDER; i++) {
        int tt = t + i - 2;                       // ORDER - LOOKAHEAD - 1 = 2
        float2 w = make_float2(0.0f, 0.0f);
        if (tt >= 0 && tt < T_DIM)
            w = spec[(size_t)(bt + i - 2) * F_DIM + f];
        float2 c = cptr[(size_t)i * F_DF];
        re = fmaf(w.x, c.x, re);
        re = fmaf(-w.y, c.y, re);
        im = fmaf(w.y, c.x, im);
        im = fmaf(w.x, c.y, im);
    }

    float a  = alpha[bt];
    float na = 1.0f - a;
    return make_float2(fmaf(re, a, s.x * na), fmaf(im, a, s.y * na));
}

__global__ void __launch_bounds__(TPB) df_coef_kernel(
    const float4* __restrict__ spec4,
    const float2* __restrict__ spec2,
    const float2* __restrict__ coefs,
    const float*  __restrict__ alpha,
    float4* __restrict__ out4)
{
    if (blockIdx.x >= SLOW_BLOCKS) {
        // ---- FAST: pure passthrough copy of upper-bin pairs ----
        int g = (blockIdx.x - SLOW_BLOCKS) * TPB + threadIdx.x;   // < NFAST always
        int rp = g / 384;
        int k  = g - rp * 384;
        // k <  192: even row, f0 = 96+2k   -> p = 481*rp + 48 + k
        // k >= 192: odd  row, f0 = 97+2(k-192) -> p = 481*rp + 97 + k
        int p = 481 * rp + k + ((k < 192) ? 48 : 97);
        __stcs(&out4[p], __ldcs(&spec4[p]));
        return;
    }

    // ---- SLOW: pairs containing at least one DF bin ----
    int s = blockIdx.x * TPB + threadIdx.x;
    if (s >= NSLOW) return;
    int rp = s / 97;
    int k  = s - rp * 97;
    int r0 = 2 * rp;

    int p, bt0, f0, bt1, f1;
    if (k < 48) {                 // even row, both elements DF
        p = 481 * rp + k;
        bt0 = r0;     f0 = 2 * k;
        bt1 = r0;     f1 = f0 + 1;
    } else if (k < 96) {          // odd row, f = 2(k-48)+1, +1
        p = 481 * rp + k + 193;
        bt0 = r0 + 1; f0 = 2 * (k - 48) + 1;
        bt1 = r0 + 1; f1 = f0 + 1;          // f1 == 96 when k == 95 (pass)
    } else {                      // boundary pair: (r0, 480) | (r0+1, 0)
        p = 481 * rp + 240;
        bt0 = r0;     f0 = 480;             // passthrough
        bt1 = r0 + 1; f1 = 0;               // DF
    }

    float4 s4 = spec4[p];
    float2 e0 = make_float2(s4.x, s4.y);
    float2 e1 = make_float2(s4.z, s4.w);

    float2 r0v = (f0 < F_DF) ? df_elem(spec2, coefs, alpha, bt0, f0, e0) : e0;
    float2 r1v = (f1 < F_DF) ? df_elem(spec2, coefs, alpha, bt1, f1, e1) : e1;

    __stcs(&out4[p], make_float4(r0v.x, r0v.y, r1v.x, r1v.y));
}

extern "C" void kernel_launch(void* const* d_in, const int* in_sizes, int n_in,
                              void* d_out, int out_size)
{
    const float4* spec4 = (const float4*)d_in[0];
    const float2* spec2 = (const float2*)d_in[0];
    const float2* coefs = (const float2*)d_in[1];
    const float*  alpha = (const float*)d_in[2];

    df_coef_kernel<<<SLOW_BLOCKS + FAST_BLOCKS, TPB>>>(
        spec4, spec2, coefs, alpha, (float4*)d_out);
}

// round 6
// speedup vs baseline: 1.3091x; 1.0670x over previous
#include <cuda_runtime.h>

// DeepFilterNet DF coef op, GB300 — R6: R5 role split + ILP=2 on fast path only.
// spec  : [B=32, 1, T=1000, F=481, 2] f32
// coefs : [B, T, 5, 96, 2] f32
// alpha : [B, T, 1] f32
// out   : same as spec; first 96 bins = 5-tap complex FIR blended with alpha.
//
// Fast-path copy was latency*concurrency bound (1 LDG in flight/thread ->
// ~5.6 TB/s). Each fast thread now streams 2 pairs, both loads issued before
// either store. Slow (DF) path unchanged — it overlaps under the copy wave.

#define B_DIM 32
#define T_DIM 1000
#define F_DIM 481
#define F_DF 96
#define ORDER 5

#define NROWPAIR 16000                 // 32000 rows / 2
#define NSLOW    (NROWPAIR * 97)       // 1,552,000 pairs
#define NFAST    (NROWPAIR * 384)      // 6,144,000 pairs
#define TPB      256
#define SLOW_BLOCKS ((NSLOW + TPB - 1) / TPB)     // 6063
#define FAST_BLOCKS (NFAST / (2 * TPB))           // 12000 (exact)

__device__ __forceinline__ float2 df_elem(
    const float2* __restrict__ spec,
    const float2* __restrict__ coefs,
    const float*  __restrict__ alpha,
    int bt, int f, float2 s)
{
    int t = bt % T_DIM;
    const float2* cptr = coefs + (size_t)bt * (ORDER * F_DF) + f;

    float re = 0.0f, im = 0.0f;
    #pragma unroll
    for (int i = 0; i < ORDER; i++) {
        int tt = t + i - 2;                       // ORDER - LOOKAHEAD - 1 = 2
        float2 w = make_float2(0.0f, 0.0f);
        if (tt >= 0 && tt < T_DIM)
            w = spec[(size_t)(bt + i - 2) * F_DIM + f];
        float2 c = cptr[(size_t)i * F_DF];
        re = fmaf(w.x, c.x, re);
        re = fmaf(-w.y, c.y, re);
        im = fmaf(w.y, c.x, im);
        im = fmaf(w.x, c.y, im);
    }

    float a  = alpha[bt];
    float na = 1.0f - a;
    return make_float2(fmaf(re, a, s.x * na), fmaf(im, a, s.y * na));
}

// map fast-path linear index g -> pair index p
__device__ __forceinline__ int fast_map(int g)
{
    int rp = g / 384;
    int k  = g - rp * 384;
    // k <  192: even row, p = 481*rp + 48 + k
    // k >= 192: odd  row, p = 481*rp + 97 + k
    return 481 * rp + k + ((k < 192) ? 48 : 97);
}

__global__ void __launch_bounds__(TPB) df_coef_kernel(
    const float4* __restrict__ spec4,
    const float2* __restrict__ spec2,
    const float2* __restrict__ coefs,
    const float*  __restrict__ alpha,
    float4* __restrict__ out4)
{
    if (blockIdx.x >= SLOW_BLOCKS) {
        // ---- FAST: passthrough copy, 2 pairs/thread, loads front-batched ----
        int fb = blockIdx.x - SLOW_BLOCKS;
        int g0 = fb * (2 * TPB) + threadIdx.x;     // < NFAST guaranteed
        int g1 = g0 + TPB;
        int p0 = fast_map(g0);
        int p1 = fast_map(g1);
        float4 v0 = __ldcs(&spec4[p0]);
        float4 v1 = __ldcs(&spec4[p1]);
        __stcs(&out4[p0], v0);
        __stcs(&out4[p1], v1);
        return;
    }

    // ---- SLOW: pairs containing at least one DF bin ----
    int s = blockIdx.x * TPB + threadIdx.x;
    if (s >= NSLOW) return;
    int rp = s / 97;
    int k  = s - rp * 97;
    int r0 = 2 * rp;

    int p, bt0, f0, bt1, f1;
    if (k < 48) {                 // even row, both elements DF
        p = 481 * rp + k;
        bt0 = r0;     f0 = 2 * k;
        bt1 = r0;     f1 = f0 + 1;
    } else if (k < 96) {          // odd row
        p = 481 * rp + k + 193;
        bt0 = r0 + 1; f0 = 2 * (k - 48) + 1;
        bt1 = r0 + 1; f1 = f0 + 1;          // f1 == 96 when k == 95 (pass)
    } else {                      // boundary pair: (r0, 480) | (r0+1, 0)
        p = 481 * rp + 240;
        bt0 = r0;     f0 = 480;             // passthrough
        bt1 = r0 + 1; f1 = 0;               // DF
    }

    float4 s4 = spec4[p];
    float2 e0 = make_float2(s4.x, s4.y);
    float2 e1 = make_float2(s4.z, s4.w);

    float2 r0v = (f0 < F_DF) ? df_elem(spec2, coefs, alpha, bt0, f0, e0) : e0;
    float2 r1v = (f1 < F_DF) ? df_elem(spec2, coefs, alpha, bt1, f1, e1) : e1;

    __stcs(&out4[p], make_float4(r0v.x, r0v.y, r1v.x, r1v.y));
}

extern "C" void kernel_launch(void* const* d_in, const int* in_sizes, int n_in,
                              void* d_out, int out_size)
{
    const float4* spec4 = (const float4*)d_in[0];
    const float2* spec2 = (const float2*)d_in[0];
    const float2* coefs = (const float2*)d_in[1];
    const float*  alpha = (const float*)d_in[2];

    df_coef_kernel<<<SLOW_BLOCKS + FAST_BLOCKS, TPB>>>(
        spec4, spec2, coefs, alpha, (float4*)d_out);
}